// round 7
// baseline (speedup 1.0000x reference)
#include <cuda_runtime.h>
#include <cuda_bf16.h>

#define N_CLASSES 9
#define N_GROUPS  2
#define N_BINS    (N_CLASSES * N_GROUPS)   // 18
#define THREADS_PER_BLOCK 256
#define CTAS_PER_SM 6
#define NUM_SMS 148

// Global scratch (no allocations). Zero-initialized at load; the last block of
// every launch resets everything, so each graph replay sees clean state.
__device__ unsigned int g_counts[N_BINS];
__device__ unsigned int g_ticket;

__device__ __forceinline__ void acc_elem(int pred, int attr,
                                         unsigned long long& acc0,
                                         unsigned long long& acc1)
{
    unsigned s = (unsigned)pred * 7u;
    unsigned long long inc = 1ULL << s;
    if (attr) acc1 += inc; else acc0 += inc;   // predicated IADD3/IADD3.X
}

__device__ __forceinline__ void flush_pair(unsigned long long& acc0,
                                           unsigned long long& acc1,
                                           unsigned int* blk)
{
    #pragma unroll
    for (int c = 0; c < N_CLASSES; c++) {
        unsigned f0 = (unsigned)(acc0 >> (7 * c)) & 0x7Fu;
        unsigned f1 = (unsigned)(acc1 >> (7 * c)) & 0x7Fu;
        atomicAdd(&blk[2 * c + 0], f0);   // warp-uniform -> REDUX-aggregated
        atomicAdd(&blk[2 * c + 1], f1);
    }
    acc0 = 0ULL;
    acc1 = 0ULL;
}

__device__ __forceinline__ int4 ldcs4(const int4* p) { return __ldcs(p); }

__global__ void __launch_bounds__(THREADS_PER_BLOCK, CTAS_PER_SM)
spd_loss_kernel(const int* __restrict__ preds,
                const int* __restrict__ attrs,
                float* __restrict__ out,
                int n, int n4, float n_total)
{
    __shared__ unsigned int blk[N_BINS];
    __shared__ unsigned int is_last;

    if (threadIdx.x < N_BINS) blk[threadIdx.x] = 0u;

    // Two accumulator pairs: x,y -> pair A; z,w -> pair B (shorter chains).
    unsigned long long a0 = 0ULL, a1 = 0ULL;
    unsigned long long b0 = 0ULL, b1 = 0ULL;

    const int4* __restrict__ p4 = (const int4*)preds;
    const int4* __restrict__ a4 = (const int4*)attrs;

    const int tid    = blockIdx.x * THREADS_PER_BLOCK + threadIdx.x;
    const int stride = gridDim.x * THREADS_PER_BLOCK;

    // Software-pipelined (depth 2) streaming loop: while consuming stage A,
    // stage B is in flight and stage C is being issued -> every warp keeps
    // loads outstanding at all times.
    int4 pA, aA, pB, aB;
    bool vA = (tid < n4);
    bool vB = (tid + stride < n4);
    if (vA) { pA = ldcs4(p4 + tid);          aA = ldcs4(a4 + tid); }
    if (vB) { pB = ldcs4(p4 + tid + stride); aB = ldcs4(a4 + tid + stride); }

    int j = tid + 2 * stride;   // index of the stage being prefetched
    int pending = 0;
    while (vA) {
        bool vC = (j < n4);
        int4 pC, aC;
        if (vC) { pC = ldcs4(p4 + j); aC = ldcs4(a4 + j); }

        acc_elem(pA.x, aA.x, a0, a1);
        acc_elem(pA.y, aA.y, a0, a1);
        acc_elem(pA.z, aA.z, b0, b1);
        acc_elem(pA.w, aA.w, b0, b1);

        // Safety flush: 2 elems/pair/iter; 50 < 127 field capacity.
        if (++pending == 25) {
            flush_pair(a0, a1, blk);
            flush_pair(b0, b1, blk);
            pending = 0;
        }

        pA = pB; aA = aB; vA = vB;
        pB = pC; aB = aC; vB = vC;
        j += stride;
    }

    // Scalar tail (n not multiple of 4) — block 0 only, tiny.
    if (blockIdx.x == 0) {
        for (int k = (n4 << 2) + threadIdx.x; k < n; k += THREADS_PER_BLOCK)
            acc_elem(preds[k], attrs[k], a0, a1);
    }

    flush_pair(a0, a1, blk);
    flush_pair(b0, b1, blk);
    __syncthreads();

    // Block totals -> global atomics
    if (threadIdx.x < N_BINS)
        atomicAdd(&g_counts[threadIdx.x], blk[threadIdx.x]);

    // Release + ticket: last block finalizes.
    __syncthreads();
    if (threadIdx.x == 0) {
        __threadfence();
        unsigned t = atomicAdd(&g_ticket, 1u);
        is_last = (t == gridDim.x - 1) ? 1u : 0u;
    }
    __syncthreads();

    if (is_last && threadIdx.x == 0) {
        __threadfence();  // acquire side
        float cb[N_BINS];
        #pragma unroll
        for (int c = 0; c < N_BINS; c++)
            cb[c] = (float)atomicAdd(&g_counts[c], 0u);  // coherent read

        float n1 = 0.0f;
        #pragma unroll
        for (int c = 0; c < N_CLASSES; c++) n1 += cb[2 * c + 1];
        float n0 = n_total - n1;

        float s = 0.0f;
        #pragma unroll
        for (int c = 0; c < N_CLASSES; c++) {
            float d = cb[2 * c] / n0 - cb[2 * c + 1] / n1;
            s += d * d;
        }
        out[0] = s;

        // Reset globals for the next graph replay.
        #pragma unroll
        for (int c = 0; c < N_BINS; c++)
            atomicExch(&g_counts[c], 0u);
        __threadfence();
        atomicExch(&g_ticket, 0u);
    }
}

extern "C" void kernel_launch(void* const* d_in, const int* in_sizes, int n_in,
                              void* d_out, int out_size)
{
    const int* preds = (const int*)d_in[0];
    const int* attrs = (const int*)d_in[1];
    float* out = (float*)d_out;
    int n  = in_sizes[0];
    int n4 = n >> 2;

    // One full wave: 148 SMs x 6 CTAs/SM (enforced by launch_bounds).
    int blocks = NUM_SMS * CTAS_PER_SM;   // 888
    int max_needed = (n4 + THREADS_PER_BLOCK - 1) / THREADS_PER_BLOCK;
    if (blocks > max_needed) blocks = max_needed;
    if (blocks < 1) blocks = 1;

    spd_loss_kernel<<<blocks, THREADS_PER_BLOCK>>>(preds, attrs, out, n, n4, (float)n);
}